// round 8
// baseline (speedup 1.0000x reference)
#include <cuda_runtime.h>
#include <cuda_fp16.h>
#include <cuda_bf16.h>
#include <cstdint>

#define BSZ 8192
#define DIM 256

// ---------------- device globals ----------------
__device__ uint8_t  g_K8[(size_t)BSZ * BSZ];        // 67 MB: K = exp(G-1) as e4m3
__device__ uint8_t  g_img8[BSZ * DIM];
__device__ uint8_t  g_txt8[BSZ * DIM];
__device__ float g_vimg[BSZ], g_vtxt[BSZ], g_uimg[BSZ], g_utxt[BSZ];
__device__ float g_rA[BSZ], g_cA[BSZ], g_rB[BSZ], g_cB[BSZ];
__device__ float g_part[BSZ];

// ---------------- asm helpers ----------------
__device__ __forceinline__ void cp_async16(uint32_t saddr, const void* gsrc) {
    asm volatile("cp.async.cg.shared.global [%0], [%1], 16;\n" :: "r"(saddr), "l"(gsrc));
}
__device__ __forceinline__ void ldsm4(uint32_t addr, uint32_t& r0, uint32_t& r1,
                                      uint32_t& r2, uint32_t& r3) {
    asm volatile("ldmatrix.sync.aligned.m8n8.x4.shared.b16 {%0,%1,%2,%3}, [%4];"
                 : "=r"(r0), "=r"(r1), "=r"(r2), "=r"(r3) : "r"(addr));
}
__device__ __forceinline__ void ldsm4t(uint32_t addr, uint32_t& r0, uint32_t& r1,
                                       uint32_t& r2, uint32_t& r3) {
    asm volatile("ldmatrix.sync.aligned.m8n8.x4.trans.shared.b16 {%0,%1,%2,%3}, [%4];"
                 : "=r"(r0), "=r"(r1), "=r"(r2), "=r"(r3) : "r"(addr));
}
__device__ __forceinline__ void mma_f16(float c[4], const uint32_t a[4],
                                        uint32_t b0, uint32_t b1) {
    asm volatile(
        "mma.sync.aligned.m16n8k16.row.col.f32.f16.f16.f32 "
        "{%0,%1,%2,%3}, {%4,%5,%6,%7}, {%8,%9}, {%0,%1,%2,%3};\n"
        : "+f"(c[0]), "+f"(c[1]), "+f"(c[2]), "+f"(c[3])
        : "r"(a[0]), "r"(a[1]), "r"(a[2]), "r"(a[3]), "r"(b0), "r"(b1));
}
__device__ __forceinline__ void mma_fp8(float c[4], const uint32_t a[4],
                                        uint32_t b0, uint32_t b1) {
    asm volatile(
        "mma.sync.aligned.m16n8k32.row.col.f32.e4m3.e4m3.f32 "
        "{%0,%1,%2,%3}, {%4,%5,%6,%7}, {%8,%9}, {%0,%1,%2,%3};\n"
        : "+f"(c[0]), "+f"(c[1]), "+f"(c[2]), "+f"(c[3])
        : "r"(a[0]), "r"(a[1]), "r"(a[2]), "r"(a[3]), "r"(b0), "r"(b1));
}
__device__ __forceinline__ __half2 cvt8x2(uint32_t w) {   // low 16 bits = 2 e4m3 -> half2
    uint32_t r;
    asm("cvt.rn.f16x2.e4m3x2 %0, %1;" : "=r"(r) : "h"((unsigned short)w));
    return *reinterpret_cast<__half2*>(&r);
}
__device__ __forceinline__ unsigned short pack_e4m3(float hi, float lo) {
    unsigned short r;  // d[7:0]=cvt(lo), d[15:8]=cvt(hi)
    asm("cvt.rn.satfinite.e4m3x2.f32 %0, %1, %2;" : "=h"(r) : "f"(hi), "f"(lo));
    return r;
}
__device__ __forceinline__ float k8_to_f(uint8_t b) {
    uint32_t r;
    asm("cvt.rn.f16x2.e4m3x2 %0, %1;" : "=r"(r) : "h"((unsigned short)b));
    return __low2float(*reinterpret_cast<__half2*>(&r));
}
__device__ __forceinline__ uint32_t swz128(uint32_t off) {
    return off ^ ((off >> 3) & 0x70);
}

// ---------------- fp32 -> e4m3 convert ----------------
__global__ void cvt8_kernel(const float* __restrict__ img, const float* __restrict__ txt) {
    int i = blockIdx.x * blockDim.x + threadIdx.x;
    if (i < BSZ * DIM / 2) {
        reinterpret_cast<unsigned short*>(g_img8)[i] = pack_e4m3(img[2 * i + 1], img[2 * i]);
        reinterpret_cast<unsigned short*>(g_txt8)[i] = pack_e4m3(txt[2 * i + 1], txt[2 * i]);
    }
}

// ================= GEMM: K = exp(img @ txt^T - 1), fp8 in, e4m3 out =================
#define SP8 272
#define NB 64
#define STRIPC 1024
#define NTILES (STRIPC / NB)
#define GEMM_SMEM_BYTES ((128 + 2 * NB) * SP8)

__global__ __launch_bounds__(256, 1) void gemm_exp_kernel() {
    extern __shared__ uint8_t sm8[];
    uint8_t* As = sm8;
    const uint32_t sAs = (uint32_t)__cvta_generic_to_shared(As);
    const uint32_t sBs = sAs + 128 * SP8;

    const int tid  = threadIdx.x;
    const int lane = tid & 31, warp = tid >> 5;
    const int g = lane >> 2, tq = lane & 3;
    const int wm = warp & 3, wn = warp >> 2;

    const int mTile  = blockIdx.y * 128;
    const int strip0 = blockIdx.x * STRIPC;

    for (int idx = tid; idx < 128 * 16; idx += 256) {
        int r = idx >> 4, c16 = idx & 15;
        *reinterpret_cast<uint4*>(As + r * SP8 + c16 * 16) =
            *reinterpret_cast<const uint4*>(g_img8 + (size_t)(mTile + r) * DIM + c16 * 16);
    }
    for (int idx = tid; idx < NB * 16; idx += 256) {
        int r = idx >> 4, c16 = idx & 15;
        cp_async16(sBs + (uint32_t)(r * SP8 + c16 * 16),
                   g_txt8 + (size_t)(strip0 + r) * DIM + c16 * 16);
    }
    asm volatile("cp.async.commit_group;\n");

    const int lrow = lane & 15;
    const int lkB  = (lane >> 4) * 16;

    for (int bt = 0; bt < NTILES; bt++) {
        if (bt + 1 < NTILES) {
            uint32_t sBd = sBs + (uint32_t)(((bt + 1) & 1) * NB * SP8);
            const int nb0 = strip0 + (bt + 1) * NB;
            for (int idx = tid; idx < NB * 16; idx += 256) {
                int r = idx >> 4, c16 = idx & 15;
                cp_async16(sBd + (uint32_t)(r * SP8 + c16 * 16),
                           g_txt8 + (size_t)(nb0 + r) * DIM + c16 * 16);
            }
            asm volatile("cp.async.commit_group;\n");
            asm volatile("cp.async.wait_group 1;\n");
        } else {
            asm volatile("cp.async.wait_group 0;\n");
        }
        __syncthreads();

        const uint32_t sBb = sBs + (uint32_t)((bt & 1) * NB * SP8);
        float c[2][4][4];
        #pragma unroll
        for (int mi = 0; mi < 2; mi++)
            #pragma unroll
            for (int ni = 0; ni < 4; ni++)
                #pragma unroll
                for (int k = 0; k < 4; k++) c[mi][ni][k] = 0.0f;

        #pragma unroll
        for (int ks = 0; ks < 8; ks++) {
            const int k0B = ks * 32;
            uint32_t a[2][4], b[4][2];
            #pragma unroll
            for (int mi = 0; mi < 2; mi++) {
                int rb = wm * 32 + mi * 16;
                uint32_t addr = sAs + (uint32_t)((rb + lrow) * SP8 + k0B + lkB);
                ldsm4(addr, a[mi][0], a[mi][1], a[mi][2], a[mi][3]);
            }
            #pragma unroll
            for (int g16 = 0; g16 < 2; g16++) {
                int nb = wn * 32 + g16 * 16;
                uint32_t q0, q1, q2, q3;
                uint32_t addr = sBb + (uint32_t)((nb + lrow) * SP8 + k0B + lkB);
                ldsm4(addr, q0, q1, q2, q3);
                b[g16 * 2][0] = q0;     b[g16 * 2][1] = q2;
                b[g16 * 2 + 1][0] = q1; b[g16 * 2 + 1][1] = q3;
            }
            #pragma unroll
            for (int mi = 0; mi < 2; mi++)
                #pragma unroll
                for (int ni = 0; ni < 4; ni++)
                    mma_fp8(c[mi][ni], a[mi], b[ni][0], b[ni][1]);
        }

        const int nTile = strip0 + bt * NB;
        #pragma unroll
        for (int mi = 0; mi < 2; mi++) {
            #pragma unroll
            for (int ni = 0; ni < 4; ni++) {
                int row0 = mTile + wm * 32 + mi * 16 + g;
                int col  = nTile + wn * 32 + ni * 8 + 2 * tq;
                unsigned short p01 = pack_e4m3(__expf(c[mi][ni][1] - 1.0f), __expf(c[mi][ni][0] - 1.0f));
                unsigned short p23 = pack_e4m3(__expf(c[mi][ni][3] - 1.0f), __expf(c[mi][ni][2] - 1.0f));
                *reinterpret_cast<unsigned short*>(g_K8 + (size_t)row0 * BSZ + col)       = p01;
                *reinterpret_cast<unsigned short*>(g_K8 + (size_t)(row0 + 8) * BSZ + col) = p23;
            }
        }
        __syncthreads();
    }
}

// ---------------- init ----------------
__global__ void init_kernel() {
    int i = blockIdx.x * blockDim.x + threadIdx.x;
    if (i < BSZ) {
        g_vimg[i] = 1.0f; g_vtxt[i] = 1.0f;
        g_rA[i] = 0.0f; g_cA[i] = 0.0f; g_rB[i] = 0.0f; g_cB[i] = 0.0f;
    }
}

// ============== tensor-core dual pass (fp8 DRAM, f16 mma core) ==============
// Per chunk: cp.async 128x64 e4m3 (8 KB) -> convert in smem to the swizzled
// f16 tile layout -> identical mma core as before (row-dir ldsm, col-dir ldsm.trans).
#define RB 128
#define CS 1024
#define CKC 64
#define NCHUNK (CS / CKC)          // 16
#define NST8 4
#define CH8 (RB * CKC)             // 8192 B fp8 chunk
#define F16B (RB * CKC * 2)        // 16384 B f16 tile
#define OFF_F16 (NST8 * CH8)       // 32768
#define OFF_X1 (OFF_F16 + 2 * F16B)        // 65536
#define OFF_X2 (OFF_X1 + (CS / 2) * 4)
#define PASS_SMEM (OFF_X2 + (RB / 2) * 4)

__global__ __launch_bounds__(256) void pass_tensor(int mode) {
    extern __shared__ char smraw[];
    uint32_t* x1p = reinterpret_cast<uint32_t*>(smraw + OFF_X1);
    uint32_t* x2p = reinterpret_cast<uint32_t*>(smraw + OFF_X2);
    const uint32_t stile = (uint32_t)__cvta_generic_to_shared(smraw);

    const int t = threadIdx.x, lane = t & 31, w = t >> 5;
    const int colbase = blockIdx.x * CS;
    const int r0 = blockIdx.y * RB;

    float* y1 = (mode == 0) ? g_rA : g_rB;
    float* y2 = (mode == 0) ? g_cA : g_cB;

    const uint8_t* Kbase = g_K8 + (size_t)r0 * BSZ + colbase;

    // fp8 chunk loader: thread u covers row u>>2, 16B col-segment (u&3)
    auto load8 = [&](int ck) {
        uint32_t dst = stile + (uint32_t)((ck & 3) * CH8);
        const uint8_t* src = Kbase + ck * CKC;
        #pragma unroll
        for (int j = 0; j < 2; j++) {
            int u = t + 256 * j;
            cp_async16(dst + (uint32_t)(u * 16),
                       src + (size_t)(u >> 2) * BSZ + (u & 3) * 16);
        }
        asm volatile("cp.async.commit_group;\n");
    };

    load8(0); load8(1); load8(2);

    if (mode == 0) {
        for (int i = t; i < CS / 2; i += 256) {
            int c = colbase + 2 * i;
            __half2 h = __floats2half2_rn(g_vimg[c], g_vimg[c + 1]);
            x1p[i] = *reinterpret_cast<uint32_t*>(&h);
        }
        if (t < RB / 2) {
            int r = r0 + 2 * t;
            __half2 h = __floats2half2_rn(g_vtxt[r], g_vtxt[r + 1]);
            x2p[t] = *reinterpret_cast<uint32_t*>(&h);
        }
    } else {
        for (int i = t; i < CS / 2; i += 256) {
            int c = colbase + 2 * i;
            __half2 h = __floats2half2_rn(1.0f / g_cA[c], 1.0f / g_cA[c + 1]);
            x1p[i] = *reinterpret_cast<uint32_t*>(&h);
        }
        if (t < RB / 2) {
            int r = r0 + 2 * t;
            __half2 h = __floats2half2_rn(1.0f / g_rA[r], 1.0f / g_rA[r + 1]);
            x2p[t] = *reinterpret_cast<uint32_t*>(&h);
        }
    }

    const uint32_t rowoff_r = (uint32_t)((16 * w + (lane & 15)) * 128 + (lane >> 4) * 16);
    const int rowc = (lane & 7) + ((lane >> 4) << 3);
    const uint32_t coloffc = (uint32_t)((w & 3) * 32 + ((lane >> 3) & 1) * 16);
    const int rbase = (w >> 2) * 64;

    float dr[4] = {0.f, 0.f, 0.f, 0.f};

    for (int i = 0; i < NCHUNK; i++) {
        if (i <= NCHUNK - 3)      { asm volatile("cp.async.wait_group 2;\n"); }
        else if (i == NCHUNK - 2) { asm volatile("cp.async.wait_group 1;\n"); }
        else                      { asm volatile("cp.async.wait_group 0;\n"); }
        __syncthreads();

        if (i + 3 < NCHUNK) load8(i + 3);

        // convert chunk i (stage i&3) -> f16 buf (i&1), swizzled tile layout
        {
            const uint4* sp = reinterpret_cast<const uint4*>(smraw + (i & 3) * CH8);
            char* fb = smraw + OFF_F16 + (i & 1) * F16B;
            #pragma unroll
            for (int j = 0; j < 2; j++) {
                int u = t + 256 * j;
                uint4 q = sp[u];
                uint32_t wd[4] = {q.x, q.y, q.z, q.w};
                uint32_t h[8];
                #pragma unroll
                for (int k2 = 0; k2 < 4; k2++) {
                    __half2 lo = cvt8x2(wd[k2]);
                    __half2 hi = cvt8x2(wd[k2] >> 16);
                    h[2 * k2]     = *reinterpret_cast<uint32_t*>(&lo);
                    h[2 * k2 + 1] = *reinterpret_cast<uint32_t*>(&hi);
                }
                uint32_t boff = (uint32_t)((u >> 2) * 128 + (u & 3) * 32);
                *reinterpret_cast<uint4*>(fb + swz128(boff))      = make_uint4(h[0], h[1], h[2], h[3]);
                *reinterpret_cast<uint4*>(fb + swz128(boff + 16)) = make_uint4(h[4], h[5], h[6], h[7]);
            }
        }
        __syncthreads();

        const uint32_t base = stile + (uint32_t)(OFF_F16 + (i & 1) * F16B);

        float dc[4] = {0.f, 0.f, 0.f, 0.f};
        #pragma unroll
        for (int p = 0; p < 4; p++) {
            uint32_t a[4];
            uint32_t off = (uint32_t)((rbase + 16 * p + rowc) * 128) + coloffc;
            ldsm4t(base + swz128(off), a[0], a[1], a[2], a[3]);
            uint32_t b0 = x2p[(rbase >> 1) + 8 * p + (lane & 3)];
            uint32_t b1 = x2p[(rbase >> 1) + 8 * p + (lane & 3) + 4];
            mma_f16(dc, a, b0, b1);
        }
        if ((lane & 3) == 0) {
            int cc = colbase + i * CKC + (w & 3) * 16 + (lane >> 2);
            atomicAdd(&y2[cc], dc[0]);
            atomicAdd(&y2[cc + 8], dc[2]);
        }

        #pragma unroll
        for (int s = 0; s < 4; s++) {
            uint32_t a[4];
            uint32_t off = rowoff_r + (uint32_t)(s * 32);
            ldsm4(base + swz128(off), a[0], a[1], a[2], a[3]);
            uint32_t b0 = x1p[i * 32 + 8 * s + (lane & 3)];
            uint32_t b1 = x1p[i * 32 + 8 * s + (lane & 3) + 4];
            mma_f16(dr, a, b0, b1);
        }
    }

    if ((lane & 3) == 0) {
        int rr = r0 + 16 * w + (lane >> 2);
        atomicAdd(&y1[rr], dr[0]);
        atomicAdd(&y1[rr + 8], dr[2]);
    }
}

// ---------------- per-iteration scalar update ----------------
__global__ void upd_uv_kernel() {
    int i = blockIdx.x * blockDim.x + threadIdx.x;
    if (i < BSZ) {
        g_uimg[i] = 1.0f / g_rA[i];
        g_utxt[i] = 1.0f / g_cA[i];

        float tt = g_vimg[i] * g_cB[i];
        float f1 = fmaxf(0.5f / tt, 1.0f);
        tt *= f1;
        float f2 = fminf(4.5f / tt, 1.0f);
        g_vimg[i] *= f1 * f2;

        float tu = g_vtxt[i] * g_rB[i];
        float h1 = fmaxf(0.5f / tu, 1.0f);
        tu *= h1;
        float h2 = fminf(4.5f / tu, 1.0f);
        g_vtxt[i] *= h1 * h2;

        g_rA[i] = 0.0f; g_cA[i] = 0.0f; g_rB[i] = 0.0f; g_cB[i] = 0.0f;
    }
}

// ---------------- finalize ----------------
__global__ void finalize1_kernel(const int* __restrict__ labels) {
    int i = blockIdx.x * blockDim.x + threadIdx.x;
    if (i < BSZ) {
        int l = labels[i];
        float p1 = g_uimg[i] * k8_to_f(g_K8[(size_t)i * BSZ + l]) * g_vimg[l];
        float p2 = g_utxt[i] * k8_to_f(g_K8[(size_t)l * BSZ + i]) * g_vtxt[l];
        float S1 = (float)BSZ + g_uimg[i] * g_rA[i];
        float S2 = (float)BSZ + g_utxt[i] * g_cA[i];
        g_part[i] = (__logf(S1) - p1) + (__logf(S2) - p2);
    }
}

__global__ void finalize2_kernel(float* __restrict__ out) {
    __shared__ float smr[1024];
    int t = threadIdx.x;
    float s = 0.0f;
    for (int i = t; i < BSZ; i += 1024) s += g_part[i];
    smr[t] = s;
    __syncthreads();
    for (int off = 512; off > 0; off >>= 1) {
        if (t < off) smr[t] += smr[t + off];
        __syncthreads();
    }
    if (t == 0) out[0] = smr[0] * (0.5f / (float)BSZ);
}

// ---------------- launch ----------------
extern "C" void kernel_launch(void* const* d_in, const int* in_sizes, int n_in,
                              void* d_out, int out_size) {
    const float* img    = (const float*)d_in[0];
    const float* txt    = (const float*)d_in[1];
    const int*   labels = (const int*)d_in[2];
    float* out = (float*)d_out;
    (void)in_sizes; (void)n_in; (void)out_size;

    cudaFuncSetAttribute(gemm_exp_kernel, cudaFuncAttributeMaxDynamicSharedMemorySize,
                         GEMM_SMEM_BYTES);
    cudaFuncSetAttribute(pass_tensor, cudaFuncAttributeMaxDynamicSharedMemorySize,
                         PASS_SMEM);

    cvt8_kernel<<<(BSZ * DIM / 2 + 255) / 256, 256>>>(img, txt);

    dim3 ggrid(BSZ / STRIPC, BSZ / 128);   // (8, 64)
    gemm_exp_kernel<<<ggrid, 256, GEMM_SMEM_BYTES>>>();

    init_kernel<<<BSZ / 256, 256>>>();

    dim3 pgrid(BSZ / CS, BSZ / RB);        // (8, 64) = 512 blocks
    for (int it = 0; it < 5; it++) {
        pass_tensor<<<pgrid, 256, PASS_SMEM>>>(0);
        pass_tensor<<<pgrid, 256, PASS_SMEM>>>(1);
        upd_uv_kernel<<<BSZ / 256, 256>>>();
    }

    pass_tensor<<<pgrid, 256, PASS_SMEM>>>(0);
    finalize1_kernel<<<BSZ / 256, 256>>>(labels);
    finalize2_kernel<<<1, 1024>>>(out);
}